// round 3
// baseline (speedup 1.0000x reference)
#include <cuda_runtime.h>

// FastQuantumLLMOptimized: per-position cross-head attention.
// x: [16384, 32, 128] f32, patterns: [32,128] f32.
//   xh = x_pos * patterns ; s = xh @ xh^T / sqrt(128); a = softmax(s); out = a @ xh
//
// One CTA (128 thr) per position, fp32 with packed fma.rn.f32x2.
//  - xh in smem as swizzled float4 granules: P(h,c) = h*32 + (c ^ ((h&8)>>1))
//  - phase 2: 4h x 4g register tiles, 2-way k-split reduced via shfl_xor(1)
//    (partner is the adjacent lane), softmax fully in-warp (shfl over gt bits)
//  - only 2 __syncthreads per CTA; no partials buffer

#define NHEADS 32
#define HD 128
#define SWZ(h) (((h) & 8) >> 1)     // granule XOR: 0 or 4
#define AT_ROW 36                    // attn row stride (floats): 144B, 16B-aligned

__device__ __forceinline__ unsigned long long pack2(float lo, float hi) {
    unsigned long long r;
    asm("mov.b64 %0, {%1, %2};" : "=l"(r) : "f"(lo), "f"(hi));
    return r;
}
__device__ __forceinline__ float2 unpack2(unsigned long long v) {
    float2 r;
    asm("mov.b64 {%0, %1}, %2;" : "=f"(r.x), "=f"(r.y) : "l"(v));
    return r;
}
__device__ __forceinline__ void fma2(unsigned long long &acc,
                                     unsigned long long a,
                                     unsigned long long b) {
    asm("fma.rn.f32x2 %0, %1, %2, %0;" : "+l"(acc) : "l"(a), "l"(b));
}

__global__ __launch_bounds__(128, 6)
void fq_attn_kernel(const float* __restrict__ x,
                    const float* __restrict__ patterns,
                    float* __restrict__ out)
{
    __shared__ __align__(16) float4 s_xh4[NHEADS * 32];       // 16 KB
    __shared__ __align__(16) float s_attn[NHEADS * AT_ROW];   // 4.5 KB

    const int tid = threadIdx.x;
    const long long pos = blockIdx.x;

    // ---------------- Phase 1: load + modulate -> swizzled smem ------------
    {
        const float4* x4 = reinterpret_cast<const float4*>(x + pos * (NHEADS * HD));
        const float4* p4 = reinterpret_cast<const float4*>(patterns);
        #pragma unroll
        for (int i = 0; i < 8; i++) {
            int idx = tid + i * 128;          // float4 index 0..1023
            float4 xv = x4[idx];
            float4 pv = __ldg(&p4[idx]);
            int h = idx >> 5;                 // warp-uniform row
            int c = idx & 31;                 // lane = chunk -> conflict-free
            float4 r;
            r.x = xv.x * pv.x; r.y = xv.y * pv.y;
            r.z = xv.z * pv.z; r.w = xv.w * pv.w;
            s_xh4[h * 32 + (c ^ SWZ(h))] = r;
        }
    }
    __syncthreads();

    // ---------------- Phase 2: scores + softmax, all in registers ----------
    // 128 threads = kt(2, interleaved k) x gt(8, 4 g-rows) x ht(8, 4 h-rows).
    {
        const int kt = tid & 1;
        const int gt = (tid >> 1) & 7;
        const int ht = tid >> 4;
        const int h0 = ht * 4;
        const int g0 = gt * 4;
        const int sa = SWZ(h0);     // uniform over the 4 h-rows
        const int sb = SWZ(g0);     // uniform over the 4 g-rows

        unsigned long long acc[4][4];
        #pragma unroll
        for (int i = 0; i < 4; i++)
            #pragma unroll
            for (int j = 0; j < 4; j++) acc[i][j] = 0ULL;

        #pragma unroll
        for (int s = 0; s < 16; s++) {
            const int c = kt + 2 * s;          // interleaved k-chunk (4 floats)
            ulonglong2 a[4];
            #pragma unroll
            for (int i = 0; i < 4; i++)
                a[i] = *reinterpret_cast<const ulonglong2*>(&s_xh4[(h0 + i) * 32 + (c ^ sa)]);
            #pragma unroll
            for (int j = 0; j < 4; j++) {
                ulonglong2 b = *reinterpret_cast<const ulonglong2*>(&s_xh4[(g0 + j) * 32 + (c ^ sb)]);
                #pragma unroll
                for (int i = 0; i < 4; i++) {
                    fma2(acc[i][j], a[i].x, b.x);
                    fma2(acc[i][j], a[i].y, b.y);
                }
            }
        }

        // collapse f32x2 lanes + reduce across the kt partner (adjacent lane)
        float v[4][4];
        #pragma unroll
        for (int i = 0; i < 4; i++)
            #pragma unroll
            for (int j = 0; j < 4; j++) {
                float2 u = unpack2(acc[i][j]);
                float p = u.x + u.y;
                p += __shfl_xor_sync(0xffffffffu, p, 1);
                v[i][j] = p * 0.08838834764831845f;   // 1/sqrt(128)
            }

        // in-warp softmax over g (j in-thread, gt via shfl on bits {2,4,8})
        float m[4], ssum[4];
        #pragma unroll
        for (int i = 0; i < 4; i++) {
            float mi = fmaxf(fmaxf(v[i][0], v[i][1]), fmaxf(v[i][2], v[i][3]));
            mi = fmaxf(mi, __shfl_xor_sync(0xffffffffu, mi, 2));
            mi = fmaxf(mi, __shfl_xor_sync(0xffffffffu, mi, 4));
            mi = fmaxf(mi, __shfl_xor_sync(0xffffffffu, mi, 8));
            m[i] = mi;
        }
        #pragma unroll
        for (int i = 0; i < 4; i++) {
            float s0 = 0.0f;
            #pragma unroll
            for (int j = 0; j < 4; j++) { v[i][j] = __expf(v[i][j] - m[i]); s0 += v[i][j]; }
            s0 += __shfl_xor_sync(0xffffffffu, s0, 2);
            s0 += __shfl_xor_sync(0xffffffffu, s0, 4);
            s0 += __shfl_xor_sync(0xffffffffu, s0, 8);
            ssum[i] = s0;
        }

        // write attn rows; kt partners hold identical values -> split i rows
        #pragma unroll
        for (int i = 0; i < 2; i++) {
            const int ii = kt * 2 + i;
            const float inv = 1.0f / ssum[ii];
            float4 a4 = make_float4(v[ii][0] * inv, v[ii][1] * inv,
                                    v[ii][2] * inv, v[ii][3] * inv);
            *reinterpret_cast<float4*>(&s_attn[(h0 + ii) * AT_ROW + g0]) = a4;
        }
    }
    __syncthreads();

    // ---------------- Phase 3: out = attn @ xh (32x128, k=32) --------------
    // 128 threads = dt(16) x ht(8).  Each thread owns d-chunks {dt, dt+16}.
    {
        const int dt = tid & 15;
        const int ht = tid >> 4;
        const int h0 = ht * 4;

        unsigned long long acc[4][4];
        #pragma unroll
        for (int i = 0; i < 4; i++)
            #pragma unroll
            for (int jp = 0; jp < 4; jp++) acc[i][jp] = 0ULL;

        #pragma unroll
        for (int gb = 0; gb < 8; gb++) {
            float4 at[4];
            #pragma unroll
            for (int i = 0; i < 4; i++)    // warp-broadcast loads
                at[i] = *reinterpret_cast<const float4*>(&s_attn[(h0 + i) * AT_ROW + gb * 4]);
            #pragma unroll
            for (int t = 0; t < 4; t++) {
                const int g = gb * 4 + t;
                const int sg = SWZ(g);
                ulonglong2 b0 = *reinterpret_cast<const ulonglong2*>(&s_xh4[g * 32 + (dt ^ sg)]);
                ulonglong2 b1 = *reinterpret_cast<const ulonglong2*>(&s_xh4[g * 32 + ((dt + 16) ^ sg)]);
                #pragma unroll
                for (int i = 0; i < 4; i++) {
                    float av = (&at[i].x)[t];
                    unsigned long long a2 = pack2(av, av);
                    fma2(acc[i][0], a2, b0.x);
                    fma2(acc[i][1], a2, b0.y);
                    fma2(acc[i][2], a2, b1.x);
                    fma2(acc[i][3], a2, b1.y);
                }
            }
        }

        float* outp = out + pos * (NHEADS * HD);
        #pragma unroll
        for (int i = 0; i < 4; i++) {
            float2 u0 = unpack2(acc[i][0]);
            float2 u1 = unpack2(acc[i][1]);
            float2 u2 = unpack2(acc[i][2]);
            float2 u3 = unpack2(acc[i][3]);
            float4 o0 = make_float4(u0.x, u0.y, u1.x, u1.y);
            float4 o1 = make_float4(u2.x, u2.y, u3.x, u3.y);
            *reinterpret_cast<float4*>(&outp[(h0 + i) * HD + dt * 4])      = o0;
            *reinterpret_cast<float4*>(&outp[(h0 + i) * HD + dt * 4 + 64]) = o1;
        }
    }
}

extern "C" void kernel_launch(void* const* d_in, const int* in_sizes, int n_in,
                              void* d_out, int out_size) {
    const float* x        = (const float*)d_in[0];
    const float* patterns = (const float*)d_in[1];
    float* out            = (float*)d_out;
    const int positions   = in_sizes[0] / (NHEADS * HD);   // 16384
    fq_attn_kernel<<<positions, 128>>>(x, patterns, out);
}

// round 4
// speedup vs baseline: 1.2198x; 1.2198x over previous
#include <cuda_runtime.h>

// FastQuantumLLMOptimized: per-position cross-head attention.
// x: [16384, 32, 128] f32, patterns: [32,128] f32.
//   xh = x_pos * patterns ; s = xh xh^T / sqrt(128); a = softmax(s); out = a xh
//
// ONE WARP per position (CTA = 2 warps = 2 positions, 41KB static smem).
// Full k per thread in phase 2 (no partials, no __syncthreads — warps fully
// independent). fp32 with packed fma.rn.f32x2.
//
// Swizzle: xh stored as float4 granules at  h*32 + (c ^ ((h>>2)&7)).
// This makes every LDS phase-group (8 lanes) hit 8 distinct bank-groups:
//   - phase-2 a-loads: rows 4ht+i over ht=0..7 -> bank-group = c ^ ht (distinct)
//   - phase-2 b-loads: address uniform per subgroup (broadcast)
//   - phase-4 b-loads: 4 consecutive chunks per subgroup (distinct)
// attn stored transposed [g][h] stride 36: conflict-free f4 stores; phase-4
// reads one broadcast float4 per g covering all 4 h-rows of the thread.

#define NHEADS 32
#define HD 128
#define AT_ROW 36

__device__ __forceinline__ unsigned long long pack2(float lo, float hi) {
    unsigned long long r;
    asm("mov.b64 %0, {%1, %2};" : "=l"(r) : "f"(lo), "f"(hi));
    return r;
}
__device__ __forceinline__ float2 unpack2(unsigned long long v) {
    float2 r;
    asm("mov.b64 {%0, %1}, %2;" : "=f"(r.x), "=f"(r.y) : "l"(v));
    return r;
}
__device__ __forceinline__ void fma2(unsigned long long &acc,
                                     unsigned long long a,
                                     unsigned long long b) {
    asm("fma.rn.f32x2 %0, %1, %2, %0;" : "+l"(acc) : "l"(a), "l"(b));
}

__global__ __launch_bounds__(64)
void fq_attn_kernel(const float* __restrict__ x,
                    const float* __restrict__ patterns,
                    float* __restrict__ out, int npos)
{
    __shared__ __align__(16) float4 s_xh4[2][NHEADS * 32];          // 2 x 16 KB
    __shared__ __align__(16) float  s_at [2][NHEADS * AT_ROW + 4];  // 2 x ~4.6 KB

    const int lane = threadIdx.x & 31;
    const int w    = threadIdx.x >> 5;
    const long long pos = 2LL * blockIdx.x + w;
    if (pos >= npos) return;

    float4* xh = s_xh4[w];
    float*  at = s_at[w];

    // ---------------- Phase 1: load + modulate -> swizzled smem ------------
    {
        const float4* x4 = reinterpret_cast<const float4*>(x + pos * (NHEADS * HD));
        const float4* p4 = reinterpret_cast<const float4*>(patterns);
        #pragma unroll 8
        for (int h = 0; h < 32; h++) {
            float4 xv = x4[h * 32 + lane];
            float4 pv = __ldg(&p4[h * 32 + lane]);
            float4 r;
            r.x = xv.x * pv.x; r.y = xv.y * pv.y;
            r.z = xv.z * pv.z; r.w = xv.w * pv.w;
            xh[h * 32 + (lane ^ ((h >> 2) & 7))] = r;
        }
    }
    __syncwarp();

    // ---------------- Phase 2: scores (32x32, k=128), full k per thread ----
    // lane = ht(8) x gt(4): thread computes 4h x 8g tile, all 128 k.
    const int ht = lane & 7;
    const int gt = lane >> 3;
    const int h0 = ht * 4;
    const int g0 = gt * 8;
    {
        unsigned long long acc[4][8];
        #pragma unroll
        for (int i = 0; i < 4; i++)
            #pragma unroll
            for (int j = 0; j < 8; j++) acc[i][j] = 0ULL;

        #pragma unroll 4
        for (int c = 0; c < 32; c++) {
            ulonglong2 a[4];
            #pragma unroll
            for (int i = 0; i < 4; i++)   // swizzle of row 4ht+i is ht (i<4)
                a[i] = *reinterpret_cast<const ulonglong2*>(&xh[(h0 + i) * 32 + (c ^ ht)]);
            #pragma unroll
            for (int j = 0; j < 8; j++) {
                const int sb = 2 * gt + (j >> 2);   // swizzle of row 8gt+j
                ulonglong2 b = *reinterpret_cast<const ulonglong2*>(&xh[(g0 + j) * 32 + (c ^ sb)]);
                #pragma unroll
                for (int i = 0; i < 4; i++) {
                    fma2(acc[i][j], a[i].x, b.x);
                    fma2(acc[i][j], a[i].y, b.y);
                }
            }
        }

        // collapse + softmax (rows h0..h0+3 live on the 4 lanes sharing ht;
        // g distributed: 8 in-thread + gt via shfl on lane bits 3,4)
        float v[4][8];
        #pragma unroll
        for (int i = 0; i < 4; i++)
            #pragma unroll
            for (int j = 0; j < 8; j++) {
                float2 u = unpack2(acc[i][j]);
                v[i][j] = (u.x + u.y) * 0.08838834764831845f;  // 1/sqrt(128)
            }

        float inv[4];
        #pragma unroll
        for (int i = 0; i < 4; i++) {
            float m = v[i][0];
            #pragma unroll
            for (int j = 1; j < 8; j++) m = fmaxf(m, v[i][j]);
            m = fmaxf(m, __shfl_xor_sync(0xffffffffu, m, 8));
            m = fmaxf(m, __shfl_xor_sync(0xffffffffu, m, 16));
            float s = 0.0f;
            #pragma unroll
            for (int j = 0; j < 8; j++) { v[i][j] = __expf(v[i][j] - m); s += v[i][j]; }
            s += __shfl_xor_sync(0xffffffffu, s, 8);
            s += __shfl_xor_sync(0xffffffffu, s, 16);
            inv[i] = 1.0f / s;
        }

        // store attn transposed: at[g*36 + h]; per j one float4 over i rows
        #pragma unroll
        for (int j = 0; j < 8; j++) {
            float4 q = make_float4(v[0][j] * inv[0], v[1][j] * inv[1],
                                   v[2][j] * inv[2], v[3][j] * inv[3]);
            *reinterpret_cast<float4*>(&at[(g0 + j) * AT_ROW + h0]) = q;
        }
    }
    __syncwarp();

    // ---------------- Phase 3: out = attn @ xh (32x128, k=32) --------------
    // lane = hq(8) x dt(4); two d-half passes; thread tile 4h x 16d per pass.
    {
        const int dt = lane & 3;
        const int hq = lane >> 2;
        const int H0 = hq * 4;
        float* outp = out + pos * (NHEADS * HD);

        for (int p = 0; p < 2; p++) {
            unsigned long long acc[4][4][2];
            #pragma unroll
            for (int i = 0; i < 4; i++)
                #pragma unroll
                for (int t = 0; t < 4; t++) { acc[i][t][0] = 0ULL; acc[i][t][1] = 0ULL; }

            #pragma unroll 4
            for (int g = 0; g < 32; g++) {
                float4 av = *reinterpret_cast<const float4*>(&at[g * AT_ROW + H0]);
                unsigned long long a2[4];
                a2[0] = pack2(av.x, av.x);
                a2[1] = pack2(av.y, av.y);
                a2[2] = pack2(av.z, av.z);
                a2[3] = pack2(av.w, av.w);
                const int sg = (g >> 2) & 7;
                #pragma unroll
                for (int t = 0; t < 4; t++) {
                    const int ch = p * 16 + t * 4 + dt;
                    ulonglong2 bb = *reinterpret_cast<const ulonglong2*>(&xh[g * 32 + (ch ^ sg)]);
                    #pragma unroll
                    for (int i = 0; i < 4; i++) {
                        fma2(acc[i][t][0], a2[i], bb.x);
                        fma2(acc[i][t][1], a2[i], bb.y);
                    }
                }
            }

            #pragma unroll
            for (int i = 0; i < 4; i++)
                #pragma unroll
                for (int t = 0; t < 4; t++) {
                    const int ch = p * 16 + t * 4 + dt;
                    float2 u0 = unpack2(acc[i][t][0]);
                    float2 u1 = unpack2(acc[i][t][1]);
                    *reinterpret_cast<float4*>(&outp[(H0 + i) * HD + ch * 4])
                        = make_float4(u0.x, u0.y, u1.x, u1.y);
                }
        }
    }
}

extern "C" void kernel_launch(void* const* d_in, const int* in_sizes, int n_in,
                              void* d_out, int out_size) {
    const float* x        = (const float*)d_in[0];
    const float* patterns = (const float*)d_in[1];
    float* out            = (float*)d_out;
    const int positions   = in_sizes[0] / (NHEADS * HD);   // 16384
    const int blocks      = (positions + 1) / 2;
    fq_attn_kernel<<<blocks, 64>>>(x, patterns, out, positions);
}

// round 5
// speedup vs baseline: 1.2249x; 1.0042x over previous
#include <cuda_runtime.h>

// FastQuantumLLMOptimized: per-position cross-head attention.
// x: [16384, 32, 128] f32, patterns: [32,128] f32.
//   xh = x_pos * patterns ; s = xh xh^T / sqrt(128); a = softmax(s); out = a xh
//
// ONE WARP per position (CTA = 2 warps = 2 positions, 41KB static smem).
// Full k per thread in phase 2 (no partials, no __syncthreads — warps fully
// independent). fp32 with packed fma.rn.f32x2.
//
// Swizzle: xh stored as float4 granules at  h*32 + (c ^ ((h>>2)&7)).
// This makes every LDS phase-group (8 lanes) hit 8 distinct bank-groups:
//   - phase-2 a-loads: rows 4ht+i over ht=0..7 -> bank-group = c ^ ht (distinct)
//   - phase-2 b-loads: address uniform per subgroup (broadcast)
//   - phase-4 b-loads: 4 consecutive chunks per subgroup (distinct)
// attn stored transposed [g][h] stride 36: conflict-free f4 stores; phase-4
// reads one broadcast float4 per g covering all 4 h-rows of the thread.

#define NHEADS 32
#define HD 128
#define AT_ROW 36

__device__ __forceinline__ unsigned long long pack2(float lo, float hi) {
    unsigned long long r;
    asm("mov.b64 %0, {%1, %2};" : "=l"(r) : "f"(lo), "f"(hi));
    return r;
}
__device__ __forceinline__ float2 unpack2(unsigned long long v) {
    float2 r;
    asm("mov.b64 {%0, %1}, %2;" : "=f"(r.x), "=f"(r.y) : "l"(v));
    return r;
}
__device__ __forceinline__ void fma2(unsigned long long &acc,
                                     unsigned long long a,
                                     unsigned long long b) {
    asm("fma.rn.f32x2 %0, %1, %2, %0;" : "+l"(acc) : "l"(a), "l"(b));
}

__global__ __launch_bounds__(64)
void fq_attn_kernel(const float* __restrict__ x,
                    const float* __restrict__ patterns,
                    float* __restrict__ out, int npos)
{
    __shared__ __align__(16) float4 s_xh4[2][NHEADS * 32];          // 2 x 16 KB
    __shared__ __align__(16) float  s_at [2][NHEADS * AT_ROW + 4];  // 2 x ~4.6 KB

    const int lane = threadIdx.x & 31;
    const int w    = threadIdx.x >> 5;
    const long long pos = 2LL * blockIdx.x + w;
    if (pos >= npos) return;

    float4* xh = s_xh4[w];
    float*  at = s_at[w];

    // ---------------- Phase 1: load + modulate -> swizzled smem ------------
    {
        const float4* x4 = reinterpret_cast<const float4*>(x + pos * (NHEADS * HD));
        const float4* p4 = reinterpret_cast<const float4*>(patterns);
        #pragma unroll 8
        for (int h = 0; h < 32; h++) {
            float4 xv = x4[h * 32 + lane];
            float4 pv = __ldg(&p4[h * 32 + lane]);
            float4 r;
            r.x = xv.x * pv.x; r.y = xv.y * pv.y;
            r.z = xv.z * pv.z; r.w = xv.w * pv.w;
            xh[h * 32 + (lane ^ ((h >> 2) & 7))] = r;
        }
    }
    __syncwarp();

    // ---------------- Phase 2: scores (32x32, k=128), full k per thread ----
    // lane = ht(8) x gt(4): thread computes 4h x 8g tile, all 128 k.
    const int ht = lane & 7;
    const int gt = lane >> 3;
    const int h0 = ht * 4;
    const int g0 = gt * 8;
    {
        unsigned long long acc[4][8];
        #pragma unroll
        for (int i = 0; i < 4; i++)
            #pragma unroll
            for (int j = 0; j < 8; j++) acc[i][j] = 0ULL;

        #pragma unroll 4
        for (int c = 0; c < 32; c++) {
            ulonglong2 a[4];
            #pragma unroll
            for (int i = 0; i < 4; i++)   // swizzle of row 4ht+i is ht (i<4)
                a[i] = *reinterpret_cast<const ulonglong2*>(&xh[(h0 + i) * 32 + (c ^ ht)]);
            #pragma unroll
            for (int j = 0; j < 8; j++) {
                const int sb = 2 * gt + (j >> 2);   // swizzle of row 8gt+j
                ulonglong2 b = *reinterpret_cast<const ulonglong2*>(&xh[(g0 + j) * 32 + (c ^ sb)]);
                #pragma unroll
                for (int i = 0; i < 4; i++) {
                    fma2(acc[i][j], a[i].x, b.x);
                    fma2(acc[i][j], a[i].y, b.y);
                }
            }
        }

        // collapse + softmax (rows h0..h0+3 live on the 4 lanes sharing ht;
        // g distributed: 8 in-thread + gt via shfl on lane bits 3,4)
        float v[4][8];
        #pragma unroll
        for (int i = 0; i < 4; i++)
            #pragma unroll
            for (int j = 0; j < 8; j++) {
                float2 u = unpack2(acc[i][j]);
                v[i][j] = (u.x + u.y) * 0.08838834764831845f;  // 1/sqrt(128)
            }

        float inv[4];
        #pragma unroll
        for (int i = 0; i < 4; i++) {
            float m = v[i][0];
            #pragma unroll
            for (int j = 1; j < 8; j++) m = fmaxf(m, v[i][j]);
            m = fmaxf(m, __shfl_xor_sync(0xffffffffu, m, 8));
            m = fmaxf(m, __shfl_xor_sync(0xffffffffu, m, 16));
            float s = 0.0f;
            #pragma unroll
            for (int j = 0; j < 8; j++) { v[i][j] = __expf(v[i][j] - m); s += v[i][j]; }
            s += __shfl_xor_sync(0xffffffffu, s, 8);
            s += __shfl_xor_sync(0xffffffffu, s, 16);
            inv[i] = 1.0f / s;
        }

        // store attn transposed: at[g*36 + h]; per j one float4 over i rows
        #pragma unroll
        for (int j = 0; j < 8; j++) {
            float4 q = make_float4(v[0][j] * inv[0], v[1][j] * inv[1],
                                   v[2][j] * inv[2], v[3][j] * inv[3]);
            *reinterpret_cast<float4*>(&at[(g0 + j) * AT_ROW + h0]) = q;
        }
    }
    __syncwarp();

    // ---------------- Phase 3: out = attn @ xh (32x128, k=32) --------------
    // lane = hq(8) x dt(4); two d-half passes; thread tile 4h x 16d per pass.
    {
        const int dt = lane & 3;
        const int hq = lane >> 2;
        const int H0 = hq * 4;
        float* outp = out + pos * (NHEADS * HD);

        for (int p = 0; p < 2; p++) {
            unsigned long long acc[4][4][2];
            #pragma unroll
            for (int i = 0; i < 4; i++)
                #pragma unroll
                for (int t = 0; t < 4; t++) { acc[i][t][0] = 0ULL; acc[i][t][1] = 0ULL; }

            #pragma unroll 4
            for (int g = 0; g < 32; g++) {
                float4 av = *reinterpret_cast<const float4*>(&at[g * AT_ROW + H0]);
                unsigned long long a2[4];
                a2[0] = pack2(av.x, av.x);
                a2[1] = pack2(av.y, av.y);
                a2[2] = pack2(av.z, av.z);
                a2[3] = pack2(av.w, av.w);
                const int sg = (g >> 2) & 7;
                #pragma unroll
                for (int t = 0; t < 4; t++) {
                    const int ch = p * 16 + t * 4 + dt;
                    ulonglong2 bb = *reinterpret_cast<const ulonglong2*>(&xh[g * 32 + (ch ^ sg)]);
                    #pragma unroll
                    for (int i = 0; i < 4; i++) {
                        fma2(acc[i][t][0], a2[i], bb.x);
                        fma2(acc[i][t][1], a2[i], bb.y);
                    }
                }
            }

            #pragma unroll
            for (int i = 0; i < 4; i++)
                #pragma unroll
                for (int t = 0; t < 4; t++) {
                    const int ch = p * 16 + t * 4 + dt;
                    float2 u0 = unpack2(acc[i][t][0]);
                    float2 u1 = unpack2(acc[i][t][1]);
                    *reinterpret_cast<float4*>(&outp[(H0 + i) * HD + ch * 4])
                        = make_float4(u0.x, u0.y, u1.x, u1.y);
                }
        }
    }
}

extern "C" void kernel_launch(void* const* d_in, const int* in_sizes, int n_in,
                              void* d_out, int out_size) {
    const float* x        = (const float*)d_in[0];
    const float* patterns = (const float*)d_in[1];
    float* out            = (float*)d_out;
    const int positions   = in_sizes[0] / (NHEADS * HD);   // 16384
    const int blocks      = (positions + 1) / 2;
    fq_attn_kernel<<<blocks, 64>>>(x, patterns, out, positions);
}